// round 2
// baseline (speedup 1.0000x reference)
#include <cuda_runtime.h>
#include <cuda_fp16.h>
#include <cstdint>

// ============ helpers ============

__device__ __forceinline__ uint32_t smem_u32(const void* p) {
    uint32_t a;
    asm("{ .reg .u64 t; cvta.to.shared.u64 t, %1; cvt.u32.u64 %0, t; }" : "=r"(a) : "l"(p));
    return a;
}

__device__ __forceinline__ void cp_async16(uint32_t saddr, const void* gaddr) {
    asm volatile("cp.async.cg.shared.global [%0], [%1], 16;" :: "r"(saddr), "l"(gaddr));
}
#define CP_COMMIT() asm volatile("cp.async.commit_group;" ::: "memory")
#define CP_WAIT(N)  asm volatile("cp.async.wait_group %0;" :: "n"(N) : "memory")

__device__ __forceinline__ void ldsm_x4(uint32_t addr, uint32_t& r0, uint32_t& r1,
                                        uint32_t& r2, uint32_t& r3) {
    asm volatile("ldmatrix.sync.aligned.m8n8.x4.shared.b16 {%0,%1,%2,%3}, [%4];"
                 : "=r"(r0), "=r"(r1), "=r"(r2), "=r"(r3) : "r"(addr));
}

__device__ __forceinline__ void mma16816(float* c, const uint32_t* a, uint32_t b0, uint32_t b1) {
    asm volatile(
        "mma.sync.aligned.m16n8k16.row.col.f32.f16.f16.f32 "
        "{%0,%1,%2,%3}, {%4,%5,%6,%7}, {%8,%9}, {%0,%1,%2,%3};"
        : "+f"(c[0]), "+f"(c[1]), "+f"(c[2]), "+f"(c[3])
        : "r"(a[0]), "r"(a[1]), "r"(a[2]), "r"(a[3]), "r"(b0), "r"(b1));
}

// ============ device scratch ============

static constexpr size_t NEL = 16ull * 1024 * 1024;  // 16 x 1024 x 1024

__device__ __half g_qhi[NEL];
__device__ __half g_qlo[NEL];
__device__ __half g_ehi[NEL];
__device__ __half g_elo[NEL];
__device__ __half g_et[NEL];    // transpose of g_ehi per batch: [b][d][k]
__device__ __half g_w[NEL];     // softmax weights, fp16
__device__ float  g_scores[NEL];

// smem tile: 128 rows x 32 halves, padded row stride 40 halves (80 B) -> conflict-free LDSM
static constexpr int ROWB = 80;
static constexpr int TILEB = 128 * ROWB;  // 10240 B

// ============ convert: f32 -> fp16 hi/lo split ============

__global__ void __launch_bounds__(256)
convert_kernel(const float4* __restrict__ src, int which) {
    __half2* hi = which ? (__half2*)g_ehi : (__half2*)g_qhi;
    __half2* lo = which ? (__half2*)g_elo : (__half2*)g_qlo;
    size_t i = (size_t)blockIdx.x * 256 + threadIdx.x;  // 0..4M-1
    float4 v = src[i];
    __half hx = __float2half_rn(v.x), hy = __float2half_rn(v.y);
    __half hz = __float2half_rn(v.z), hw = __float2half_rn(v.w);
    __half lx = __float2half_rn(v.x - __half2float(hx));
    __half ly = __float2half_rn(v.y - __half2float(hy));
    __half lz = __float2half_rn(v.z - __half2float(hz));
    __half lw = __float2half_rn(v.w - __half2float(hw));
    hi[i * 2]     = __halves2half2(hx, hy);
    hi[i * 2 + 1] = __halves2half2(hz, hw);
    lo[i * 2]     = __halves2half2(lx, ly);
    lo[i * 2 + 1] = __halves2half2(lz, lw);
}

// ============ transpose E_hi [b][k][d] -> g_et [b][d][k] ============

__global__ void __launch_bounds__(256)
transpose_kernel() {
    __shared__ __half ts[64][66];
    int b = blockIdx.z;
    int d0 = blockIdx.x << 6, k0 = blockIdx.y << 6;
    size_t boff = (size_t)b << 20;
    int tid = threadIdx.x;
    int c2 = tid & 31, rq = tid >> 5;

    const __half* src = g_ehi + boff;
    #pragma unroll
    for (int i = 0; i < 8; i++) {
        int k = i * 8 + rq;
        __half2 v = *(const __half2*)(src + (size_t)(k0 + k) * 1024 + d0 + c2 * 2);
        ts[k][c2 * 2]     = __low2half(v);
        ts[k][c2 * 2 + 1] = __high2half(v);
    }
    __syncthreads();
    __half* dst = g_et + boff;
    #pragma unroll
    for (int i = 0; i < 8; i++) {
        int d = i * 8 + rq;
        __half2 o = __halves2half2(ts[c2 * 2][d], ts[c2 * 2 + 1][d]);
        *(__half2*)(dst + (size_t)(d0 + d) * 1024 + k0 + c2 * 2) = o;
    }
}

// ============ GEMM1: scores = Q @ E^T via 3-term fp16 split ============
// CTA 128x128, 8 warps (2 M x 4 N), warp tile 64x32, k-chunk 32, 2-stage cp.async.

__device__ __forceinline__ void g1_load(uint32_t base, int tid, int kc,
                                        const __half* gA0, const __half* gA1,
                                        const __half* gB0, const __half* gB1) {
    #pragma unroll
    for (int i = 0; i < 2; i++) {
        int cid = i * 256 + tid;            // 0..511
        int row = cid >> 2, seg = cid & 3;
        uint32_t off = row * ROWB + seg * 16;
        size_t go = (size_t)row * 1024 + kc * 32 + seg * 8;
        cp_async16(base + 0 * TILEB + off, gA0 + go);
        cp_async16(base + 1 * TILEB + off, gA1 + go);
        cp_async16(base + 2 * TILEB + off, gB0 + go);
        cp_async16(base + 3 * TILEB + off, gB1 + go);
    }
    CP_COMMIT();
}

__global__ void __launch_bounds__(256, 1)
gemm1_kernel() {
    extern __shared__ char smem[];
    uint32_t sb = smem_u32(smem);
    int tid = threadIdx.x, wid = tid >> 5, lane = tid & 31;
    int wm = wid >> 2, wn = wid & 3;
    int b = blockIdx.z;
    int m0 = blockIdx.y << 7, n0 = blockIdx.x << 7;
    size_t boff = (size_t)b << 20;

    const __half* gA0 = g_qhi + boff + (size_t)m0 * 1024;
    const __half* gA1 = g_qlo + boff + (size_t)m0 * 1024;
    const __half* gB0 = g_ehi + boff + (size_t)n0 * 1024;
    const __half* gB1 = g_elo + boff + (size_t)n0 * 1024;

    float c[4][4][4];
    #pragma unroll
    for (int i = 0; i < 4; i++)
        #pragma unroll
        for (int j = 0; j < 4; j++)
            #pragma unroll
            for (int k = 0; k < 4; k++) c[i][j][k] = 0.f;

    g1_load(sb, tid, 0, gA0, gA1, gB0, gB1);

    int lr = lane & 15;
    uint32_t lkoff = (lane >> 4) * 16;  // bytes

    for (int kc = 0; kc < 32; kc++) {
        int s = kc & 1;
        if (kc + 1 < 32) {
            g1_load(sb + (s ^ 1) * 4 * TILEB, tid, kc + 1, gA0, gA1, gB0, gB1);
            CP_WAIT(1);
        } else {
            CP_WAIT(0);
        }
        __syncthreads();

        uint32_t abase = sb + s * 4 * TILEB;
        #pragma unroll
        for (int ks = 0; ks < 2; ks++) {
            uint32_t koff = ks * 32 + lkoff;
            uint32_t ah[4][4], al[4][4], bh[2][4], bl[2][4];
            #pragma unroll
            for (int mt = 0; mt < 4; mt++) {
                uint32_t a = abase + (wm * 64 + mt * 16 + lr) * ROWB + koff;
                ldsm_x4(a, ah[mt][0], ah[mt][1], ah[mt][2], ah[mt][3]);
                ldsm_x4(a + TILEB, al[mt][0], al[mt][1], al[mt][2], al[mt][3]);
            }
            #pragma unroll
            for (int p = 0; p < 2; p++) {
                uint32_t a = abase + 2 * TILEB + (wn * 32 + p * 16 + lr) * ROWB + koff;
                ldsm_x4(a, bh[p][0], bh[p][1], bh[p][2], bh[p][3]);
                ldsm_x4(a + TILEB, bl[p][0], bl[p][1], bl[p][2], bl[p][3]);
            }
            #pragma unroll
            for (int mt = 0; mt < 4; mt++)
                #pragma unroll
                for (int p = 0; p < 2; p++)
                    #pragma unroll
                    for (int q = 0; q < 2; q++) {
                        float* cc = c[mt][p * 2 + q];
                        mma16816(cc, ah[mt], bh[p][q], bh[p][q + 2]);
                        mma16816(cc, ah[mt], bl[p][q], bl[p][q + 2]);
                        mma16816(cc, al[mt], bh[p][q], bh[p][q + 2]);
                    }
        }
        __syncthreads();
    }

    int r0 = m0 + wm * 64 + (lane >> 2);
    int col = n0 + wn * 32 + (lane & 3) * 2;
    #pragma unroll
    for (int mt = 0; mt < 4; mt++)
        #pragma unroll
        for (int nt = 0; nt < 4; nt++) {
            size_t base = boff + (size_t)(r0 + mt * 16) * 1024 + col + nt * 8;
            *(float2*)(g_scores + base) = make_float2(c[mt][nt][0], c[mt][nt][1]);
            *(float2*)(g_scores + base + 8 * 1024) = make_float2(c[mt][nt][2], c[mt][nt][3]);
        }
}

// ============ softmax: fp32 rows of g_scores -> fp16 g_w ============

__global__ void __launch_bounds__(256)
softmax_kernel() {
    __shared__ float red[40];
    size_t row = blockIdx.x;
    const float4* p = (const float4*)(g_scores + (row << 10));
    int t = threadIdx.x, wid = t >> 5, lane = t & 31;

    float4 v = p[t];
    float m = fmaxf(fmaxf(v.x, v.y), fmaxf(v.z, v.w));
    #pragma unroll
    for (int o = 16; o; o >>= 1) m = fmaxf(m, __shfl_xor_sync(0xffffffffu, m, o));
    if (lane == 0) red[wid] = m;
    __syncthreads();
    if (t == 0) {
        float mm = red[0];
        #pragma unroll
        for (int i = 1; i < 8; i++) mm = fmaxf(mm, red[i]);
        red[8] = mm;
    }
    __syncthreads();
    float mx = red[8];

    float4 e = make_float4(__expf(v.x - mx), __expf(v.y - mx),
                           __expf(v.z - mx), __expf(v.w - mx));
    float s = e.x + e.y + e.z + e.w;
    #pragma unroll
    for (int o = 16; o; o >>= 1) s += __shfl_xor_sync(0xffffffffu, s, o);
    if (lane == 0) red[16 + wid] = s;
    __syncthreads();
    if (t == 0) {
        float ss = red[16];
        #pragma unroll
        for (int i = 1; i < 8; i++) ss += red[16 + i];
        red[24] = 1.0f / ss;
    }
    __syncthreads();
    float inv = red[24];

    __half2* w = (__half2*)(g_w + (row << 10));
    w[t * 2]     = __floats2half2_rn(e.x * inv, e.y * inv);
    w[t * 2 + 1] = __floats2half2_rn(e.z * inv, e.w * inv);
}

// ============ GEMM2: out = W @ V (V = E_hi, via g_et), single fp16 term ============

__device__ __forceinline__ void g2_load(uint32_t base, int tid, int kc,
                                        const __half* gA, const __half* gB) {
    #pragma unroll
    for (int i = 0; i < 2; i++) {
        int cid = i * 256 + tid;
        int row = cid >> 2, seg = cid & 3;
        uint32_t off = row * ROWB + seg * 16;
        size_t go = (size_t)row * 1024 + kc * 32 + seg * 8;
        cp_async16(base + off, gA + go);
        cp_async16(base + TILEB + off, gB + go);
    }
    CP_COMMIT();
}

__global__ void __launch_bounds__(256, 2)
gemm2_kernel(float* __restrict__ O) {
    extern __shared__ char smem[];
    uint32_t sb = smem_u32(smem);
    int tid = threadIdx.x, wid = tid >> 5, lane = tid & 31;
    int wm = wid >> 2, wn = wid & 3;
    int b = blockIdx.z;
    int m0 = blockIdx.y << 7, n0 = blockIdx.x << 7;
    size_t boff = (size_t)b << 20;

    const __half* gA = g_w + boff + (size_t)m0 * 1024;
    const __half* gB = g_et + boff + (size_t)n0 * 1024;

    float c[4][4][4];
    #pragma unroll
    for (int i = 0; i < 4; i++)
        #pragma unroll
        for (int j = 0; j < 4; j++)
            #pragma unroll
            for (int k = 0; k < 4; k++) c[i][j][k] = 0.f;

    g2_load(sb, tid, 0, gA, gB);

    int lr = lane & 15;
    uint32_t lkoff = (lane >> 4) * 16;

    for (int kc = 0; kc < 32; kc++) {
        int s = kc & 1;
        if (kc + 1 < 32) {
            g2_load(sb + (s ^ 1) * 2 * TILEB, tid, kc + 1, gA, gB);
            CP_WAIT(1);
        } else {
            CP_WAIT(0);
        }
        __syncthreads();

        uint32_t abase = sb + s * 2 * TILEB;
        #pragma unroll
        for (int ks = 0; ks < 2; ks++) {
            uint32_t koff = ks * 32 + lkoff;
            uint32_t ah[4][4], bh[2][4];
            #pragma unroll
            for (int mt = 0; mt < 4; mt++) {
                uint32_t a = abase + (wm * 64 + mt * 16 + lr) * ROWB + koff;
                ldsm_x4(a, ah[mt][0], ah[mt][1], ah[mt][2], ah[mt][3]);
            }
            #pragma unroll
            for (int p = 0; p < 2; p++) {
                uint32_t a = abase + TILEB + (wn * 32 + p * 16 + lr) * ROWB + koff;
                ldsm_x4(a, bh[p][0], bh[p][1], bh[p][2], bh[p][3]);
            }
            #pragma unroll
            for (int mt = 0; mt < 4; mt++)
                #pragma unroll
                for (int p = 0; p < 2; p++)
                    #pragma unroll
                    for (int q = 0; q < 2; q++)
                        mma16816(c[mt][p * 2 + q], ah[mt], bh[p][q], bh[p][q + 2]);
        }
        __syncthreads();
    }

    int r0 = m0 + wm * 64 + (lane >> 2);
    int col = n0 + wn * 32 + (lane & 3) * 2;
    #pragma unroll
    for (int mt = 0; mt < 4; mt++)
        #pragma unroll
        for (int nt = 0; nt < 4; nt++) {
            size_t base = boff + (size_t)(r0 + mt * 16) * 1024 + col + nt * 8;
            *(float2*)(O + base) = make_float2(c[mt][nt][0], c[mt][nt][1]);
            *(float2*)(O + base + 8 * 1024) = make_float2(c[mt][nt][2], c[mt][nt][3]);
        }
}

// ============ launcher ============

extern "C" void kernel_launch(void* const* d_in, const int* in_sizes, int n_in,
                              void* d_out, int out_size) {
    const float* dec = (const float*)d_in[0];   // decoder_hidden  [16,1024,1024]
    const float* enc = (const float*)d_in[1];   // encoder_outputs [16,1024,1024]
    float* out = (float*)d_out;

    cudaFuncSetAttribute(gemm1_kernel, cudaFuncAttributeMaxDynamicSharedMemorySize, 8 * TILEB);
    cudaFuncSetAttribute(gemm2_kernel, cudaFuncAttributeMaxDynamicSharedMemorySize, 4 * TILEB);

    convert_kernel<<<16384, 256>>>((const float4*)dec, 0);
    convert_kernel<<<16384, 256>>>((const float4*)enc, 1);
    transpose_kernel<<<dim3(16, 16, 16), 256>>>();
    gemm1_kernel<<<dim3(8, 8, 16), 256, 8 * TILEB>>>();
    softmax_kernel<<<16384, 256>>>();
    gemm2_kernel<<<dim3(8, 8, 16), 256, 4 * TILEB>>>(out);
}

// round 3
// speedup vs baseline: 1.7661x; 1.7661x over previous
#include <cuda_runtime.h>
#include <cuda_fp16.h>
#include <cstdint>

// ============ helpers ============

__device__ __forceinline__ uint32_t smem_u32(const void* p) {
    uint32_t a;
    asm("{ .reg .u64 t; cvta.to.shared.u64 t, %1; cvt.u32.u64 %0, t; }" : "=r"(a) : "l"(p));
    return a;
}

__device__ __forceinline__ void cp_async16(uint32_t saddr, const void* gaddr) {
    asm volatile("cp.async.cg.shared.global [%0], [%1], 16;" :: "r"(saddr), "l"(gaddr));
}
#define CP_COMMIT() asm volatile("cp.async.commit_group;" ::: "memory")
#define CP_WAIT(N)  asm volatile("cp.async.wait_group %0;" :: "n"(N) : "memory")

__device__ __forceinline__ void ldsm_x4(uint32_t addr, uint32_t& r0, uint32_t& r1,
                                        uint32_t& r2, uint32_t& r3) {
    asm volatile("ldmatrix.sync.aligned.m8n8.x4.shared.b16 {%0,%1,%2,%3}, [%4];"
                 : "=r"(r0), "=r"(r1), "=r"(r2), "=r"(r3) : "r"(addr));
}

__device__ __forceinline__ void mma16816(float* c, const uint32_t* a, uint32_t b0, uint32_t b1) {
    asm volatile(
        "mma.sync.aligned.m16n8k16.row.col.f32.f16.f16.f32 "
        "{%0,%1,%2,%3}, {%4,%5,%6,%7}, {%8,%9}, {%0,%1,%2,%3};"
        : "+f"(c[0]), "+f"(c[1]), "+f"(c[2]), "+f"(c[3])
        : "r"(a[0]), "r"(a[1]), "r"(a[2]), "r"(a[3]), "r"(b0), "r"(b1));
}

// ============ device scratch ============

static constexpr size_t NEL = 16ull * 1024 * 1024;  // 16 x 1024 x 1024

__device__ __half g_qhi[NEL];
__device__ __half g_qlo[NEL];
__device__ __half g_ehi[NEL];
__device__ __half g_elo[NEL];
__device__ __half g_et[NEL];    // transpose of g_ehi per batch: [b][d][k]
__device__ __half g_w[NEL];     // softmax weights, fp16
__device__ float  g_scores[NEL];

// smem tile: 128 rows x 32 halves, padded row stride 40 halves (80 B) -> conflict-free LDSM
static constexpr int ROWB = 80;
static constexpr int TILEB = 128 * ROWB;  // 10240 B

// ============ convert Q: f32 -> fp16 hi/lo split ============

__global__ void __launch_bounds__(256)
convert_q_kernel(const float4* __restrict__ src) {
    __half2* hi = (__half2*)g_qhi;
    __half2* lo = (__half2*)g_qlo;
    size_t i = (size_t)blockIdx.x * 256 + threadIdx.x;
    float4 v = src[i];
    __half hx = __float2half_rn(v.x), hy = __float2half_rn(v.y);
    __half hz = __float2half_rn(v.z), hw = __float2half_rn(v.w);
    hi[i * 2]     = __halves2half2(hx, hy);
    hi[i * 2 + 1] = __halves2half2(hz, hw);
    lo[i * 2]     = __floats2half2_rn(v.x - __half2float(hx), v.y - __half2float(hy));
    lo[i * 2 + 1] = __floats2half2_rn(v.z - __half2float(hz), v.w - __half2float(hw));
}

// ============ convert E: f32 -> hi/lo + transposed hi (fused) ============
// grid (16 d-tiles, 16 k-tiles, 16 batches), 64x64 tile per block.

__global__ void __launch_bounds__(256)
convert_e_kernel(const float* __restrict__ enc) {
    __shared__ __half ts[64][65];
    int b = blockIdx.z;
    int d0 = blockIdx.x << 6, k0 = blockIdx.y << 6;
    size_t boff = (size_t)b << 20;
    int tid = threadIdx.x;
    int f4id = tid & 15, rr = tid >> 4;

    #pragma unroll
    for (int pass = 0; pass < 4; pass++) {
        int k = pass * 16 + rr;
        size_t go = boff + (size_t)(k0 + k) * 1024 + d0 + f4id * 4;
        float4 v = *(const float4*)(enc + go);
        __half hx = __float2half_rn(v.x), hy = __float2half_rn(v.y);
        __half hz = __float2half_rn(v.z), hw = __float2half_rn(v.w);
        __half2 h2a = __halves2half2(hx, hy), h2b = __halves2half2(hz, hw);
        *(__half2*)(g_ehi + go)     = h2a;
        *(__half2*)(g_ehi + go + 2) = h2b;
        *(__half2*)(g_elo + go)     = __floats2half2_rn(v.x - __half2float(hx), v.y - __half2float(hy));
        *(__half2*)(g_elo + go + 2) = __floats2half2_rn(v.z - __half2float(hz), v.w - __half2float(hw));
        int dc = f4id * 4;
        ts[k][dc] = hx; ts[k][dc + 1] = hy; ts[k][dc + 2] = hz; ts[k][dc + 3] = hw;
    }
    __syncthreads();
    int lane = tid & 31;
    #pragma unroll
    for (int pass = 0; pass < 8; pass++) {
        int dd = pass * 8 + (tid >> 5);
        int kk = lane * 2;
        __half2 o = __halves2half2(ts[kk][dd], ts[kk + 1][dd]);
        *(__half2*)(g_et + boff + (size_t)(d0 + dd) * 1024 + k0 + kk) = o;
    }
}

// ============ GEMM1: scores = Q @ E^T via 3-term fp16 split ============
// CTA 128x128, 8 warps (2 M x 4 N), warp tile 64x32, k-chunk 32, 2-stage, 2 CTAs/SM.

__device__ __forceinline__ void g1_load(uint32_t base, int tid, int kc,
                                        const __half* gA0, const __half* gA1,
                                        const __half* gB0, const __half* gB1) {
    #pragma unroll
    for (int i = 0; i < 2; i++) {
        int cid = i * 256 + tid;            // 0..511
        int row = cid >> 2, seg = cid & 3;
        uint32_t off = row * ROWB + seg * 16;
        size_t go = (size_t)row * 1024 + kc * 32 + seg * 8;
        cp_async16(base + 0 * TILEB + off, gA0 + go);
        cp_async16(base + 1 * TILEB + off, gA1 + go);
        cp_async16(base + 2 * TILEB + off, gB0 + go);
        cp_async16(base + 3 * TILEB + off, gB1 + go);
    }
    CP_COMMIT();
}

__global__ void __launch_bounds__(256, 2)
gemm1_kernel() {
    extern __shared__ char smem[];
    uint32_t sb = smem_u32(smem);
    int tid = threadIdx.x, wid = tid >> 5, lane = tid & 31;
    int wm = wid >> 2, wn = wid & 3;
    int b = blockIdx.z;
    int m0 = blockIdx.y << 7, n0 = blockIdx.x << 7;
    size_t boff = (size_t)b << 20;

    const __half* gA0 = g_qhi + boff + (size_t)m0 * 1024;
    const __half* gA1 = g_qlo + boff + (size_t)m0 * 1024;
    const __half* gB0 = g_ehi + boff + (size_t)n0 * 1024;
    const __half* gB1 = g_elo + boff + (size_t)n0 * 1024;

    float c[4][4][4];
    #pragma unroll
    for (int i = 0; i < 4; i++)
        #pragma unroll
        for (int j = 0; j < 4; j++)
            #pragma unroll
            for (int k = 0; k < 4; k++) c[i][j][k] = 0.f;

    g1_load(sb, tid, 0, gA0, gA1, gB0, gB1);

    int lr = lane & 15;
    uint32_t lkoff = (lane >> 4) * 16;  // bytes

    for (int kc = 0; kc < 32; kc++) {
        int s = kc & 1;
        if (kc + 1 < 32) {
            g1_load(sb + (s ^ 1) * 4 * TILEB, tid, kc + 1, gA0, gA1, gB0, gB1);
            CP_WAIT(1);
        } else {
            CP_WAIT(0);
        }
        __syncthreads();

        uint32_t abase = sb + s * 4 * TILEB;
        #pragma unroll
        for (int ks = 0; ks < 2; ks++) {
            uint32_t koff = ks * 32 + lkoff;
            uint32_t ah[4][4], al[4][4], bh[2][4], bl[2][4];
            #pragma unroll
            for (int mt = 0; mt < 4; mt++) {
                uint32_t a = abase + (wm * 64 + mt * 16 + lr) * ROWB + koff;
                ldsm_x4(a, ah[mt][0], ah[mt][1], ah[mt][2], ah[mt][3]);
                ldsm_x4(a + TILEB, al[mt][0], al[mt][1], al[mt][2], al[mt][3]);
            }
            #pragma unroll
            for (int p = 0; p < 2; p++) {
                uint32_t a = abase + 2 * TILEB + (wn * 32 + p * 16 + lr) * ROWB + koff;
                ldsm_x4(a, bh[p][0], bh[p][1], bh[p][2], bh[p][3]);
                ldsm_x4(a + TILEB, bl[p][0], bl[p][1], bl[p][2], bl[p][3]);
            }
            #pragma unroll
            for (int mt = 0; mt < 4; mt++)
                #pragma unroll
                for (int p = 0; p < 2; p++)
                    #pragma unroll
                    for (int q = 0; q < 2; q++) {
                        float* cc = c[mt][p * 2 + q];
                        mma16816(cc, ah[mt], bh[p][q], bh[p][q + 2]);
                        mma16816(cc, ah[mt], bl[p][q], bl[p][q + 2]);
                        mma16816(cc, al[mt], bh[p][q], bh[p][q + 2]);
                    }
        }
        __syncthreads();
    }

    int r0 = m0 + wm * 64 + (lane >> 2);
    int col = n0 + wn * 32 + (lane & 3) * 2;
    #pragma unroll
    for (int mt = 0; mt < 4; mt++)
        #pragma unroll
        for (int nt = 0; nt < 4; nt++) {
            size_t base = boff + (size_t)(r0 + mt * 16) * 1024 + col + nt * 8;
            *(float2*)(g_scores + base) = make_float2(c[mt][nt][0], c[mt][nt][1]);
            *(float2*)(g_scores + base + 8 * 1024) = make_float2(c[mt][nt][2], c[mt][nt][3]);
        }
}

// ============ softmax: fp32 rows of g_scores -> fp16 g_w ============

__global__ void __launch_bounds__(256)
softmax_kernel() {
    __shared__ float red[40];
    size_t row = blockIdx.x;
    const float4* p = (const float4*)(g_scores + (row << 10));
    int t = threadIdx.x, wid = t >> 5, lane = t & 31;

    float4 v = p[t];
    float m = fmaxf(fmaxf(v.x, v.y), fmaxf(v.z, v.w));
    #pragma unroll
    for (int o = 16; o; o >>= 1) m = fmaxf(m, __shfl_xor_sync(0xffffffffu, m, o));
    if (lane == 0) red[wid] = m;
    __syncthreads();
    if (t == 0) {
        float mm = red[0];
        #pragma unroll
        for (int i = 1; i < 8; i++) mm = fmaxf(mm, red[i]);
        red[8] = mm;
    }
    __syncthreads();
    float mx = red[8];

    float4 e = make_float4(__expf(v.x - mx), __expf(v.y - mx),
                           __expf(v.z - mx), __expf(v.w - mx));
    float s = e.x + e.y + e.z + e.w;
    #pragma unroll
    for (int o = 16; o; o >>= 1) s += __shfl_xor_sync(0xffffffffu, s, o);
    if (lane == 0) red[16 + wid] = s;
    __syncthreads();
    if (t == 0) {
        float ss = red[16];
        #pragma unroll
        for (int i = 1; i < 8; i++) ss += red[16 + i];
        red[24] = 1.0f / ss;
    }
    __syncthreads();
    float inv = red[24];

    __half2* w = (__half2*)(g_w + (row << 10));
    w[t * 2]     = __floats2half2_rn(e.x * inv, e.y * inv);
    w[t * 2 + 1] = __floats2half2_rn(e.z * inv, e.w * inv);
}

// ============ GEMM2: out = W @ V (V = E_hi, via g_et), 3-stage pipeline ============

__device__ __forceinline__ void g2_load(uint32_t base, int tid, int kc,
                                        const __half* gA, const __half* gB) {
    #pragma unroll
    for (int i = 0; i < 2; i++) {
        int cid = i * 256 + tid;
        int row = cid >> 2, seg = cid & 3;
        uint32_t off = row * ROWB + seg * 16;
        size_t go = (size_t)row * 1024 + kc * 32 + seg * 8;
        cp_async16(base + off, gA + go);
        cp_async16(base + TILEB + off, gB + go);
    }
    CP_COMMIT();
}

__global__ void __launch_bounds__(256, 2)
gemm2_kernel(float* __restrict__ O) {
    extern __shared__ char smem[];
    uint32_t sb = smem_u32(smem);
    int tid = threadIdx.x, wid = tid >> 5, lane = tid & 31;
    int wm = wid >> 2, wn = wid & 3;
    int b = blockIdx.z;
    int m0 = blockIdx.y << 7, n0 = blockIdx.x << 7;
    size_t boff = (size_t)b << 20;

    const __half* gA = g_w + boff + (size_t)m0 * 1024;
    const __half* gB = g_et + boff + (size_t)n0 * 1024;

    float c[4][4][4];
    #pragma unroll
    for (int i = 0; i < 4; i++)
        #pragma unroll
        for (int j = 0; j < 4; j++)
            #pragma unroll
            for (int k = 0; k < 4; k++) c[i][j][k] = 0.f;

    // 3-stage prologue
    g2_load(sb + 0 * 2 * TILEB, tid, 0, gA, gB);
    g2_load(sb + 1 * 2 * TILEB, tid, 1, gA, gB);

    int lr = lane & 15;
    uint32_t lkoff = (lane >> 4) * 16;

    int slot = 0;
    for (int kc = 0; kc < 32; kc++) {
        if (kc < 31) { CP_WAIT(1); } else { CP_WAIT(0); }
        __syncthreads();

        uint32_t abase = sb + slot * 2 * TILEB;
        #pragma unroll
        for (int ks = 0; ks < 2; ks++) {
            uint32_t koff = ks * 32 + lkoff;
            uint32_t ah[4][4], bh[2][4];
            #pragma unroll
            for (int mt = 0; mt < 4; mt++) {
                uint32_t a = abase + (wm * 64 + mt * 16 + lr) * ROWB + koff;
                ldsm_x4(a, ah[mt][0], ah[mt][1], ah[mt][2], ah[mt][3]);
            }
            #pragma unroll
            for (int p = 0; p < 2; p++) {
                uint32_t a = abase + TILEB + (wn * 32 + p * 16 + lr) * ROWB + koff;
                ldsm_x4(a, bh[p][0], bh[p][1], bh[p][2], bh[p][3]);
            }
            #pragma unroll
            for (int mt = 0; mt < 4; mt++)
                #pragma unroll
                for (int p = 0; p < 2; p++)
                    #pragma unroll
                    for (int q = 0; q < 2; q++)
                        mma16816(c[mt][p * 2 + q], ah[mt], bh[p][q], bh[p][q + 2]);
        }

        if (kc + 2 < 32) {
            int ns = kc + 2 - ((kc + 2) / 3) * 3;  // (kc+2) % 3
            g2_load(sb + ns * 2 * TILEB, tid, kc + 2, gA, gB);
        }
        slot = (slot == 2) ? 0 : slot + 1;
    }

    int r0 = m0 + wm * 64 + (lane >> 2);
    int col = n0 + wn * 32 + (lane & 3) * 2;
    #pragma unroll
    for (int mt = 0; mt < 4; mt++)
        #pragma unroll
        for (int nt = 0; nt < 4; nt++) {
            size_t base = boff + (size_t)(r0 + mt * 16) * 1024 + col + nt * 8;
            *(float2*)(O + base) = make_float2(c[mt][nt][0], c[mt][nt][1]);
            *(float2*)(O + base + 8 * 1024) = make_float2(c[mt][nt][2], c[mt][nt][3]);
        }
}

// ============ launcher ============

extern "C" void kernel_launch(void* const* d_in, const int* in_sizes, int n_in,
                              void* d_out, int out_size) {
    const float* dec = (const float*)d_in[0];   // decoder_hidden  [16,1024,1024]
    const float* enc = (const float*)d_in[1];   // encoder_outputs [16,1024,1024]
    float* out = (float*)d_out;

    cudaFuncSetAttribute(gemm1_kernel, cudaFuncAttributeMaxDynamicSharedMemorySize, 8 * TILEB);
    cudaFuncSetAttribute(gemm2_kernel, cudaFuncAttributeMaxDynamicSharedMemorySize, 6 * TILEB);

    convert_q_kernel<<<16384, 256>>>((const float4*)dec);
    convert_e_kernel<<<dim3(16, 16, 16), 256>>>(enc);
    gemm1_kernel<<<dim3(8, 8, 16), 256, 8 * TILEB>>>();
    softmax_kernel<<<16384, 256>>>();
    gemm2_kernel<<<dim3(8, 8, 16), 256, 6 * TILEB>>>(out);
}